// round 15
// baseline (speedup 1.0000x reference)
#include <cuda_runtime.h>
#include <cuda_fp16.h>
#include <cstdint>

#define N_NODES 50000
#define N_EDGES 1600000
#define FDIM    128
#define CAP     128          // per-node edge bucket capacity (max degree ~58)

#define GEMM_BLOCKS ((N_NODES + 63) / 64)            // 782 (64 rows per block)
#define SCAT_BLOCKS ((N_EDGES / 4 + 255) / 256)      // 1563
#define PACK_BLOCKS 196
#define WDWS_BLOCKS 32
#define WPAD        136      // Wt row pad (halfs) -> conflict-free scalar LDS
#define WT_U4       ((FDIM * WPAD) / 8)              // 2176 uint4

// Scratch (static __device__ arrays: allocation-free per harness rules)
static __device__ __half2 g_hh[(size_t)N_NODES * (FDIM / 2)];   // 12.8 MB
static __device__ float g_sd[N_NODES];
static __device__ float g_ss[N_NODES];
static __device__ float g_wd[FDIM];      // W @ a_dst
static __device__ float g_ws[FDIM];      // W @ a_src
static __device__ uint4 g_wt4[WT_U4];    // packed fp16 Wt
static __device__ int   g_cnt[N_NODES];
static __device__ int2  g_csr[(size_t)N_NODES * CAP];           // (src, score-bits)

#define FMA_F32X2(d, a, b, c) \
    asm("fma.rn.f32x2 %0, %1, %2, %3;" : "=l"(d) : "l"(a), "l"(b), "l"(c))

__device__ __forceinline__ unsigned long long pack_f2(float2 v) {
    return *reinterpret_cast<unsigned long long*>(&v);
}
__device__ __forceinline__ uint32_t f2_to_h2(float2 v) {
    __half2 h = __floats2half2_rn(v.x, v.y);
    return *reinterpret_cast<uint32_t*>(&h);
}

// ---------------------------------------------------------------------------
// Prep: pack W -> fp16 Wt (WPAD layout), zero counters, wd/ws = W @ a_{dst,src}
// ---------------------------------------------------------------------------
__global__ __launch_bounds__(256) void prep_kernel(
    const float* __restrict__ W, const float* __restrict__ attn)
{
    if (blockIdx.x < PACK_BLOCKS) {
        int i = blockIdx.x * 256 + threadIdx.x;
        if (i < FDIM * FDIM) {
            int k = i >> 7, n = i & 127;
            reinterpret_cast<__half*>(g_wt4)[n * WPAD + k] = __float2half_rn(W[i]);
        }
        if (i < N_NODES) g_cnt[i] = 0;
    } else {
        int warp = threadIdx.x >> 5;
        int lane = threadIdx.x & 31;
        int o = (blockIdx.x - PACK_BLOCKS) * 8 + warp;   // 0..255
        int k = o & 127;
        int which = o >> 7;
        float4 wv = reinterpret_cast<const float4*>(W + k * FDIM)[lane];
        float4 av = reinterpret_cast<const float4*>(attn + which * FDIM)[lane];
        float d = wv.x * av.x + wv.y * av.y + wv.z * av.z + wv.w * av.w;
        #pragma unroll
        for (int off = 16; off; off >>= 1)
            d += __shfl_xor_sync(0xffffffffu, d, off);
        if (lane == 0) {
            if (which == 0) g_wd[k] = d; else g_ws[k] = d;
        }
    }
}

// ---------------------------------------------------------------------------
// Per-node scores: sd[n] = X[n]·wd, ss[n] = X[n]·ws. One warp per node.
// (fp32-exact: equals fp32 h·a since score factorizes through W)
// ---------------------------------------------------------------------------
__global__ __launch_bounds__(256) void score_kernel(const float* __restrict__ X)
{
    int n    = (blockIdx.x * blockDim.x + threadIdx.x) >> 5;
    int lane = threadIdx.x & 31;
    if (n >= N_NODES) return;
    float4 xv = reinterpret_cast<const float4*>(X + (size_t)n * FDIM)[lane];
    float4 wd = reinterpret_cast<const float4*>(g_wd)[lane];
    float4 ws = reinterpret_cast<const float4*>(g_ws)[lane];
    float pd = xv.x * wd.x + xv.y * wd.y + xv.z * wd.z + xv.w * wd.w;
    float ps = xv.x * ws.x + xv.y * ws.y + xv.z * ws.z + xv.w * ws.w;
    #pragma unroll
    for (int off = 16; off; off >>= 1) {
        pd += __shfl_xor_sync(0xffffffffu, pd, off);
        ps += __shfl_xor_sync(0xffffffffu, ps, off);
    }
    if (lane == 0) { g_sd[n] = pd; g_ss[n] = ps; }
}

// ---------------------------------------------------------------------------
// h = X @ W via HMMA, N-split across warp pairs (round-14 form minus the
// score epilogue). Warp = 16 rows x 64 cols; 4 CTAs/SM.
// ---------------------------------------------------------------------------
__global__ __launch_bounds__(256, 4) void gemm_h_mma(const float* __restrict__ X)
{
    __shared__ __align__(16) __half wt[FDIM * WPAD];   // 34.8 KB

    {   // fill from pre-packed Wt as uint4
        const uint4* s = g_wt4;
        uint4* d = reinterpret_cast<uint4*>(wt);
        #pragma unroll
        for (int r = 0; r < 9; r++) {
            int i = r * 256 + threadIdx.x;
            if (i < WT_U4) d[i] = s[i];
        }
    }
    __syncthreads();

    const int warp = threadIdx.x >> 5;
    const int lane = threadIdx.x & 31;
    const int pair = warp >> 1;
    const int sub  = warp & 1;
    const int g = lane >> 2;
    const int t = lane & 3;

    const int m0   = blockIdx.x * 64 + pair * 16;
    const int row0 = m0 + g;
    const int row1 = m0 + g + 8;
    const int lr0  = min(row0, N_NODES - 1);
    const int lr1  = min(row1, N_NODES - 1);

    const float* x0 = X + (size_t)lr0 * FDIM;
    const float* x1 = X + (size_t)lr1 * FDIM;
    const uint32_t* wtw = reinterpret_cast<const uint32_t*>(wt);

    float acc[8][4];
    #pragma unroll
    for (int n = 0; n < 8; n++)
        acc[n][0] = acc[n][1] = acc[n][2] = acc[n][3] = 0.f;

    #pragma unroll
    for (int kc = 0; kc < 8; kc++) {
        int k0 = kc * 16 + 2 * t;
        uint32_t a0 = f2_to_h2(*reinterpret_cast<const float2*>(x0 + k0));
        uint32_t a1 = f2_to_h2(*reinterpret_cast<const float2*>(x1 + k0));
        uint32_t a2 = f2_to_h2(*reinterpret_cast<const float2*>(x0 + k0 + 8));
        uint32_t a3 = f2_to_h2(*reinterpret_cast<const float2*>(x1 + k0 + 8));
        #pragma unroll
        for (int ntl = 0; ntl < 8; ntl++) {
            int nt = sub * 8 + ntl;
            int bw = (nt * 8 + g) * (WPAD / 2) + kc * 8 + t;   // 4g+t: conflict-free
            uint32_t b0 = wtw[bw];
            uint32_t b1 = wtw[bw + 4];
            asm volatile(
                "mma.sync.aligned.m16n8k16.row.col.f32.f16.f16.f32 "
                "{%0,%1,%2,%3}, {%4,%5,%6,%7}, {%8,%9}, {%0,%1,%2,%3};"
                : "+f"(acc[ntl][0]), "+f"(acc[ntl][1]),
                  "+f"(acc[ntl][2]), "+f"(acc[ntl][3])
                : "r"(a0), "r"(a1), "r"(a2), "r"(a3), "r"(b0), "r"(b1));
        }
    }

    #pragma unroll
    for (int ntl = 0; ntl < 8; ntl++) {
        int nt = sub * 8 + ntl;
        if (row0 < N_NODES)
            g_hh[(unsigned int)row0 * 64u + nt * 4 + t] =
                __floats2half2_rn(acc[ntl][0], acc[ntl][1]);
        if (row1 < N_NODES)
            g_hh[(unsigned int)row1 * 64u + nt * 4 + t] =
                __floats2half2_rn(acc[ntl][2], acc[ntl][3]);
    }
}

// ---------------------------------------------------------------------------
// Scatter (measured-good form): 4 edges/thread, direct buckets.
// ---------------------------------------------------------------------------
__global__ __launch_bounds__(256) void scatter_kernel(const int4* __restrict__ E4) {
    int i = blockIdx.x * 256 + threadIdx.x;
    if (i >= N_EDGES / 4) return;
    int4 ea = E4[i * 2];
    int4 eb = E4[i * 2 + 1];

    #define SCORE(D, S, OUTV) { \
        float sc = g_sd[D] + g_ss[S]; \
        sc = sc > 0.f ? sc : 0.2f * sc; \
        sc = fminf(2.f, fmaxf(-2.f, sc)); \
        OUTV = __expf(sc); }

    float s0, s1, s2, s3;
    SCORE(ea.x, ea.y, s0)
    SCORE(ea.z, ea.w, s1)
    SCORE(eb.x, eb.y, s2)
    SCORE(eb.z, eb.w, s3)
    #undef SCORE

    int p0 = atomicAdd(&g_cnt[ea.x], 1);
    int p1 = atomicAdd(&g_cnt[ea.z], 1);
    int p2 = atomicAdd(&g_cnt[eb.x], 1);
    int p3 = atomicAdd(&g_cnt[eb.z], 1);
    g_csr[(unsigned int)ea.x * CAP + p0] = make_int2(ea.y, __float_as_int(s0));
    g_csr[(unsigned int)ea.z * CAP + p1] = make_int2(ea.w, __float_as_int(s1));
    g_csr[(unsigned int)eb.x * CAP + p2] = make_int2(eb.y, __float_as_int(s2));
    g_csr[(unsigned int)eb.z * CAP + p3] = make_int2(eb.w, __float_as_int(s3));
}

// ---------------------------------------------------------------------------
// Agg (round-10 measured-good form — FINAL).
// ---------------------------------------------------------------------------
__global__ __launch_bounds__(256) void agg_kernel(float* __restrict__ out) {
    int w    = (blockIdx.x * blockDim.x + threadIdx.x) >> 5;
    int lane = threadIdx.x & 31;
    if (w >= N_NODES) return;

    int cnt = g_cnt[w];
    const int2* row = g_csr + (unsigned int)w * CAP;
    const uint2* hh = reinterpret_cast<const uint2*>(g_hh);

    unsigned long long accA = 0ull, accB = 0ull;
    float ssum = 0.f;

    #define ACCUM(V, WT) { \
        float2 f0 = __half22float2(*reinterpret_cast<__half2*>(&(V).x)); \
        float2 f1 = __half22float2(*reinterpret_cast<__half2*>(&(V).y)); \
        unsigned long long ww = pack_f2(make_float2((WT), (WT))); \
        FMA_F32X2(accA, ww, pack_f2(f0), accA); \
        FMA_F32X2(accB, ww, pack_f2(f1), accB); }

    int e = 0;
    for (; e + 4 <= cnt; e += 4) {
        int4 m01 = *reinterpret_cast<const int4*>(row + e);
        int4 m23 = *reinterpret_cast<const int4*>(row + e + 2);
        float w0 = __int_as_float(m01.y), w1 = __int_as_float(m01.w);
        float w2 = __int_as_float(m23.y), w3 = __int_as_float(m23.w);
        uint2 v0 = hh[(unsigned int)m01.x * 32u + lane];
        uint2 v1 = hh[(unsigned int)m01.z * 32u + lane];
        uint2 v2 = hh[(unsigned int)m23.x * 32u + lane];
        uint2 v3 = hh[(unsigned int)m23.z * 32u + lane];
        ACCUM(v0, w0) ACCUM(v1, w1) ACCUM(v2, w2) ACCUM(v3, w3)
        ssum += (w0 + w1) + (w2 + w3);
    }
    for (; e < cnt; e++) {
        int2 ee = row[e];
        float w0 = __int_as_float(ee.y);
        uint2 v0 = hh[(unsigned int)ee.x * 32u + lane];
        ACCUM(v0, w0)
        ssum += w0;
    }
    #undef ACCUM

    float2 rA = *reinterpret_cast<float2*>(&accA);
    float2 rB = *reinterpret_cast<float2*>(&accB);
    float inv = (ssum > 0.f) ? (1.f / ssum) : 0.f;
    reinterpret_cast<float4*>(out)[(unsigned int)w * 32u + lane] =
        make_float4(rA.x * inv, rA.y * inv, rB.x * inv, rB.y * inv);
}

// ---------------------------------------------------------------------------
// DAG: prep -> { gemm_h (main)  ||  score -> scatter (s2) } -> agg
// Stream/events lazily created on the first (uncaptured) call and reused:
// the per-call WORK is identical on every call (same kernels, same deps) —
// only the fork/join topology is expressed. s2 is NonBlocking so the only
// cross-stream ordering is via the recorded events (graph-capture legal).
// ---------------------------------------------------------------------------
extern "C" void kernel_launch(void* const* d_in, const int* in_sizes, int n_in,
                              void* d_out, int out_size)
{
    const float* X    = (const float*)d_in[0];   // node_states (50000,128)
    const int4*  E4   = (const int4*) d_in[1];   // edges as 2-edge packs
    const float* W    = (const float*)d_in[2];   // kernel (128,128)
    const float* attn = (const float*)d_in[3];   // kernel_attention (256,1)
    float* out = (float*)d_out;

    static cudaStream_t s2 = nullptr;
    static cudaEvent_t ev_fork = nullptr, ev_join = nullptr;
    if (s2 == nullptr) {
        cudaStreamCreateWithFlags(&s2, cudaStreamNonBlocking);
        cudaEventCreateWithFlags(&ev_fork, cudaEventDisableTiming);
        cudaEventCreateWithFlags(&ev_join, cudaEventDisableTiming);
    }

    prep_kernel<<<PACK_BLOCKS + WDWS_BLOCKS, 256>>>(W, attn);
    cudaEventRecord(ev_fork, 0);
    cudaStreamWaitEvent(s2, ev_fork, 0);

    // branch B (s2): scores -> edge scatter
    score_kernel<<<(N_NODES * 32 + 255) / 256, 256, 0, s2>>>(X);
    scatter_kernel<<<SCAT_BLOCKS, 256, 0, s2>>>(E4);
    cudaEventRecord(ev_join, s2);

    // branch A (main): h GEMM — runs concurrently with branch B
    gemm_h_mma<<<GEMM_BLOCKS, 256>>>(X);

    cudaStreamWaitEvent(0, ev_join, 0);
    agg_kernel<<<(N_NODES * 32 + 255) / 256, 256>>>(out);
}

// round 16
// speedup vs baseline: 1.0230x; 1.0230x over previous
#include <cuda_runtime.h>
#include <cuda_fp16.h>
#include <cstdint>

#define N_NODES 50000
#define N_EDGES 1600000
#define FDIM    128
#define CAP     128          // per-node edge bucket capacity (max degree ~58)

#define GEMM_BLOCKS ((N_NODES + 63) / 64)            // 782 (64 rows per block)
#define SCAT_BLOCKS ((N_EDGES / 4 + 255) / 256)      // 1563
#define PREP_BLOCKS 196
#define WPAD        136      // Wt row pad (halfs) -> conflict-free scalar LDS
#define WT_U4       ((FDIM * WPAD) / 8)              // 2176 uint4

// Scratch (static __device__ arrays: allocation-free per harness rules)
static __device__ __half2 g_hh[(size_t)N_NODES * (FDIM / 2)];   // 12.8 MB
static __device__ float g_sd[N_NODES];
static __device__ float g_ss[N_NODES];
static __device__ uint4 g_wt4[WT_U4];                            // packed fp16 Wt
static __device__ int   g_cnt[N_NODES];
static __device__ int2  g_csr[(size_t)N_NODES * CAP];           // (src, score-bits)

#define FMA_F32X2(d, a, b, c) \
    asm("fma.rn.f32x2 %0, %1, %2, %3;" : "=l"(d) : "l"(a), "l"(b), "l"(c))

__device__ __forceinline__ unsigned long long pack_f2(float2 v) {
    return *reinterpret_cast<unsigned long long*>(&v);
}
__device__ __forceinline__ uint32_t f2_to_h2(float2 v) {
    __half2 h = __floats2half2_rn(v.x, v.y);
    return *reinterpret_cast<uint32_t*>(&h);
}

// ---------------------------------------------------------------------------
// Prep: pack W -> fp16 Wt[n][k] (WPAD layout) in global; zero bucket counters.
// ---------------------------------------------------------------------------
__global__ __launch_bounds__(256) void prep_kernel(const float* __restrict__ W) {
    int i = blockIdx.x * 256 + threadIdx.x;
    if (i < FDIM * FDIM) {
        int k = i >> 7, n = i & 127;
        reinterpret_cast<__half*>(g_wt4)[n * WPAD + k] = __float2half_rn(W[i]);
    }
    if (i < N_NODES) g_cnt[i] = 0;
}

// ---------------------------------------------------------------------------
// GEMM + scores via HMMA, N-split across warp pairs (round-14 measured-good):
// warp = 16 rows x 64 cols, 4 CTAs/SM; score dots fused in the epilogue.
// ---------------------------------------------------------------------------
__global__ __launch_bounds__(256, 4) void gemm_score_mma(
    const float* __restrict__ X, const float* __restrict__ attn)
{
    __shared__ __align__(16) __half wt[FDIM * WPAD];   // 34.8 KB
    __shared__ float sred[8][16][2];                   // [warp][row][pd,ps]

    {   // fast fill: copy pre-packed Wt as uint4
        const uint4* s = g_wt4;
        uint4* d = reinterpret_cast<uint4*>(wt);
        #pragma unroll
        for (int r = 0; r < 9; r++) {
            int i = r * 256 + threadIdx.x;
            if (i < WT_U4) d[i] = s[i];
        }
    }
    __syncthreads();

    const int warp = threadIdx.x >> 5;
    const int lane = threadIdx.x & 31;
    const int pair = warp >> 1;        // 0..3 (16 rows each)
    const int sub  = warp & 1;         // 0: cols 0-63, 1: cols 64-127
    const int g = lane >> 2;
    const int t = lane & 3;

    const int m0   = blockIdx.x * 64 + pair * 16;
    const int row0 = m0 + g;
    const int row1 = m0 + g + 8;
    const int lr0  = min(row0, N_NODES - 1);
    const int lr1  = min(row1, N_NODES - 1);

    const float* x0 = X + (size_t)lr0 * FDIM;
    const float* x1 = X + (size_t)lr1 * FDIM;
    const uint32_t* wtw = reinterpret_cast<const uint32_t*>(wt);   // 68 words/row

    float acc[8][4];
    #pragma unroll
    for (int n = 0; n < 8; n++)
        acc[n][0] = acc[n][1] = acc[n][2] = acc[n][3] = 0.f;

    #pragma unroll
    for (int kc = 0; kc < 8; kc++) {
        int k0 = kc * 16 + 2 * t;
        uint32_t a0 = f2_to_h2(*reinterpret_cast<const float2*>(x0 + k0));
        uint32_t a1 = f2_to_h2(*reinterpret_cast<const float2*>(x1 + k0));
        uint32_t a2 = f2_to_h2(*reinterpret_cast<const float2*>(x0 + k0 + 8));
        uint32_t a3 = f2_to_h2(*reinterpret_cast<const float2*>(x1 + k0 + 8));
        #pragma unroll
        for (int ntl = 0; ntl < 8; ntl++) {
            int nt = sub * 8 + ntl;
            int bw = (nt * 8 + g) * (WPAD / 2) + kc * 8 + t;   // 4g+t: conflict-free
            uint32_t b0 = wtw[bw];
            uint32_t b1 = wtw[bw + 4];
            asm volatile(
                "mma.sync.aligned.m16n8k16.row.col.f32.f16.f16.f32 "
                "{%0,%1,%2,%3}, {%4,%5,%6,%7}, {%8,%9}, {%0,%1,%2,%3};"
                : "+f"(acc[ntl][0]), "+f"(acc[ntl][1]),
                  "+f"(acc[ntl][2]), "+f"(acc[ntl][3])
                : "r"(a0), "r"(a1), "r"(a2), "r"(a3), "r"(b0), "r"(b1));
        }
    }

    // Epilogue: h fp16 store + partial score dots over this warp's 64 cols
    float pd0 = 0.f, ps0 = 0.f, pd1 = 0.f, ps1 = 0.f;
    #pragma unroll
    for (int ntl = 0; ntl < 8; ntl++) {
        int nt = sub * 8 + ntl;
        int c0 = nt * 8 + 2 * t;
        float2 ad = *reinterpret_cast<const float2*>(attn + c0);
        float2 as = *reinterpret_cast<const float2*>(attn + FDIM + c0);
        pd0 += acc[ntl][0] * ad.x + acc[ntl][1] * ad.y;
        ps0 += acc[ntl][0] * as.x + acc[ntl][1] * as.y;
        pd1 += acc[ntl][2] * ad.x + acc[ntl][3] * ad.y;
        ps1 += acc[ntl][2] * as.x + acc[ntl][3] * as.y;
        if (row0 < N_NODES)
            g_hh[(unsigned int)row0 * 64u + nt * 4 + t] =
                __floats2half2_rn(acc[ntl][0], acc[ntl][1]);
        if (row1 < N_NODES)
            g_hh[(unsigned int)row1 * 64u + nt * 4 + t] =
                __floats2half2_rn(acc[ntl][2], acc[ntl][3]);
    }
    #pragma unroll
    for (int off = 1; off < 4; off <<= 1) {
        pd0 += __shfl_xor_sync(0xffffffffu, pd0, off);
        ps0 += __shfl_xor_sync(0xffffffffu, ps0, off);
        pd1 += __shfl_xor_sync(0xffffffffu, pd1, off);
        ps1 += __shfl_xor_sync(0xffffffffu, ps1, off);
    }
    if (t == 0) {
        sred[warp][g][0]     = pd0;  sred[warp][g][1]     = ps0;
        sred[warp][g + 8][0] = pd1;  sred[warp][g + 8][1] = ps1;
    }
    __syncthreads();

    if (threadIdx.x < 128) {
        int p    = threadIdx.x >> 5;
        int r    = (threadIdx.x >> 1) & 15;
        int comp = threadIdx.x & 1;
        int grow = blockIdx.x * 64 + p * 16 + r;
        if (grow < N_NODES) {
            float v = sred[2 * p][r][comp] + sred[2 * p + 1][r][comp];
            if (comp == 0) g_sd[grow] = v; else g_ss[grow] = v;
        }
    }
}

// ---------------------------------------------------------------------------
// Scatter with PDL: hoist the coalesced E4 loads BEFORE the grid-dependency
// sync so they overlap the gemm's tail; then gather scores and bucket-write.
// ---------------------------------------------------------------------------
__global__ __launch_bounds__(256) void scatter_kernel(const int4* __restrict__ E4) {
    int i = blockIdx.x * 256 + threadIdx.x;
    int4 ea, eb;
    bool valid = (i < N_EDGES / 4);
    if (valid) {
        ea = E4[i * 2];           // independent of upstream kernels
        eb = E4[i * 2 + 1];
    }

    cudaGridDependencySynchronize();   // wait for gemm's g_sd/g_ss (+ g_cnt)

    if (!valid) return;

    #define SCORE(D, S, OUTV) { \
        float sc = g_sd[D] + g_ss[S]; \
        sc = sc > 0.f ? sc : 0.2f * sc; \
        sc = fminf(2.f, fmaxf(-2.f, sc)); \
        OUTV = __expf(sc); }

    float s0, s1, s2, s3;
    SCORE(ea.x, ea.y, s0)
    SCORE(ea.z, ea.w, s1)
    SCORE(eb.x, eb.y, s2)
    SCORE(eb.z, eb.w, s3)
    #undef SCORE

    int p0 = atomicAdd(&g_cnt[ea.x], 1);
    int p1 = atomicAdd(&g_cnt[ea.z], 1);
    int p2 = atomicAdd(&g_cnt[eb.x], 1);
    int p3 = atomicAdd(&g_cnt[eb.z], 1);
    g_csr[(unsigned int)ea.x * CAP + p0] = make_int2(ea.y, __float_as_int(s0));
    g_csr[(unsigned int)ea.z * CAP + p1] = make_int2(ea.w, __float_as_int(s1));
    g_csr[(unsigned int)eb.x * CAP + p2] = make_int2(eb.y, __float_as_int(s2));
    g_csr[(unsigned int)eb.z * CAP + p3] = make_int2(eb.w, __float_as_int(s3));
}

// ---------------------------------------------------------------------------
// Agg (round-10 measured-good form — FINAL) + PDL attr (index setup hoisted).
// ---------------------------------------------------------------------------
__global__ __launch_bounds__(256) void agg_kernel(float* __restrict__ out) {
    int w    = (blockIdx.x * blockDim.x + threadIdx.x) >> 5;
    int lane = threadIdx.x & 31;
    const int2* row = g_csr + (unsigned int)w * CAP;
    const uint2* hh = reinterpret_cast<const uint2*>(g_hh);

    cudaGridDependencySynchronize();   // wait for scatter (g_cnt/g_csr) + gemm

    if (w >= N_NODES) return;
    int cnt = g_cnt[w];

    unsigned long long accA = 0ull, accB = 0ull;
    float ssum = 0.f;

    #define ACCUM(V, WT) { \
        float2 f0 = __half22float2(*reinterpret_cast<__half2*>(&(V).x)); \
        float2 f1 = __half22float2(*reinterpret_cast<__half2*>(&(V).y)); \
        unsigned long long ww = pack_f2(make_float2((WT), (WT))); \
        FMA_F32X2(accA, ww, pack_f2(f0), accA); \
        FMA_F32X2(accB, ww, pack_f2(f1), accB); }

    int e = 0;
    for (; e + 4 <= cnt; e += 4) {
        int4 m01 = *reinterpret_cast<const int4*>(row + e);
        int4 m23 = *reinterpret_cast<const int4*>(row + e + 2);
        float w0 = __int_as_float(m01.y), w1 = __int_as_float(m01.w);
        float w2 = __int_as_float(m23.y), w3 = __int_as_float(m23.w);
        uint2 v0 = hh[(unsigned int)m01.x * 32u + lane];
        uint2 v1 = hh[(unsigned int)m01.z * 32u + lane];
        uint2 v2 = hh[(unsigned int)m23.x * 32u + lane];
        uint2 v3 = hh[(unsigned int)m23.z * 32u + lane];
        ACCUM(v0, w0) ACCUM(v1, w1) ACCUM(v2, w2) ACCUM(v3, w3)
        ssum += (w0 + w1) + (w2 + w3);
    }
    for (; e < cnt; e++) {
        int2 ee = row[e];
        float w0 = __int_as_float(ee.y);
        uint2 v0 = hh[(unsigned int)ee.x * 32u + lane];
        ACCUM(v0, w0)
        ssum += w0;
    }
    #undef ACCUM

    float2 rA = *reinterpret_cast<float2*>(&accA);
    float2 rB = *reinterpret_cast<float2*>(&accB);
    float inv = (ssum > 0.f) ? (1.f / ssum) : 0.f;
    reinterpret_cast<float4*>(out)[(unsigned int)w * 32u + lane] =
        make_float4(rA.x * inv, rA.y * inv, rB.x * inv, rB.y * inv);
}

// ---------------------------------------------------------------------------
// prep -> gemm(+scores) -> scatter (PDL) -> agg (PDL)
// ---------------------------------------------------------------------------
extern "C" void kernel_launch(void* const* d_in, const int* in_sizes, int n_in,
                              void* d_out, int out_size)
{
    const float* X    = (const float*)d_in[0];   // node_states (50000,128)
    const int4*  E4   = (const int4*) d_in[1];   // edges as 2-edge packs
    const float* W    = (const float*)d_in[2];   // kernel (128,128)
    const float* attn = (const float*)d_in[3];   // kernel_attention (256,1)
    float* out = (float*)d_out;

    prep_kernel<<<PREP_BLOCKS, 256>>>(W);
    gemm_score_mma<<<GEMM_BLOCKS, 256>>>(X, attn);

    cudaLaunchAttribute pdl[1];
    pdl[0].id = cudaLaunchAttributeProgrammaticStreamSerialization;
    pdl[0].val.programmaticStreamSerializationAllowed = 1;

    {   // scatter with PDL: E4 loads overlap gemm's tail
        cudaLaunchConfig_t cfg = {};
        cfg.gridDim  = dim3(SCAT_BLOCKS);
        cfg.blockDim = dim3(256);
        cfg.attrs    = pdl;
        cfg.numAttrs = 1;
        cudaLaunchKernelEx(&cfg, scatter_kernel, E4);
    }
    {   // agg with PDL: launch/setup overlaps scatter's tail
        cudaLaunchConfig_t cfg = {};
        cfg.gridDim  = dim3((N_NODES * 32 + 255) / 256);
        cfg.blockDim = dim3(256);
        cfg.attrs    = pdl;
        cfg.numAttrs = 1;
        cudaLaunchKernelEx(&cfg, agg_kernel, out);
    }
}